// round 15
// baseline (speedup 1.0000x reference)
#include <cuda_runtime.h>
#include <cuda_fp16.h>
#include <cstdint>
#include <math.h>
#include <mma.h>

using namespace nvcuda;

#define SEQ    1024
#define NBATCH 2
#define BSTOT  2048      // B*S
#define NH     64
#define HD     32
#define DS     64
#define KPROJ  4432
#define DI     2048
#define DM     1024
#define EPSV   1e-5f

#define CHUNK  64
#define NC     16        // SEQ / CHUNK

// offsets inside one proj row of length KPROJ
#define OFF_Z   0
#define OFF_X   2048
#define OFF_B   4096
#define OFF_C   4160
#define OFF_DT  4224
#define OFF_A   4288
#define OFF_TR  4352
#define OFF_ANG 4416

// scratch layout (float units)
#define PROJ_OFF 0ull
#define AARR_OFF 9076736ull      // + BSTOT*KPROJ
#define GB_OFF   9207808ull      // + BSTOT*NH
#define CM_OFF   17596416ull     // + BSTOT*NH*DS
#define Y_OFF    25985024ull     // + BSTOT*NH*DS
#define HST_OFF  30179328ull     // + BSTOT*DI
#define PBUF_OFF 34373632ull     // + NBATCH*NH*NC*HD*DS
#define UH_OFF   34504704ull     // + BSTOT*NH            : half copy of u
#define WIH_OFF  35553280ull     // + BSTOT*DM/2          : half copy of W_in
#define WOH_OFF  37822464ull     // + KPROJ*DM/2          : half copy of W_out
#define YH_OFF   38871040ull     // + DM*DI/2             : half copy of Y
#define SCRATCH_TOTAL 40968192ull

// converter segment sizes (elements)
#define N_U  (BSTOT * DM)
#define N_WI (KPROJ * DM)
#define N_WO (DM * DI)

__device__ __align__(16) float g_scratch[SCRATCH_TOTAL];

__device__ __forceinline__ float softplusf(float x) {
    return x > 20.f ? x : log1pf(expf(x));
}
__device__ __forceinline__ float sigmoidf_(float x) {
    return 1.f / (1.f + expf(-x));
}

__device__ __forceinline__ void cp_async16h(__half* smem_dst, const __half* gsrc, bool pred) {
    unsigned int saddr = (unsigned int)__cvta_generic_to_shared(smem_dst);
    int sz = pred ? 16 : 0;
    asm volatile("cp.async.cg.shared.global [%0], [%1], 16, %2;\n"
                 :: "r"(saddr), "l"(gsrc), "r"(sz));
}
__device__ __forceinline__ void cp_async16f(float* smem_dst, const float* gsrc) {
    unsigned int saddr = (unsigned int)__cvta_generic_to_shared(smem_dst);
    asm volatile("cp.async.cg.shared.global [%0], [%1], 16;\n"
                 :: "r"(saddr), "l"(gsrc));
}
__device__ __forceinline__ void cp_async4f(float* smem_dst, const float* gsrc) {
    unsigned int saddr = (unsigned int)__cvta_generic_to_shared(smem_dst);
    asm volatile("cp.async.ca.shared.global [%0], [%1], 4;\n"
                 :: "r"(saddr), "l"(gsrc));
}
#define CP_COMMIT() asm volatile("cp.async.commit_group;\n" ::: "memory")
#define CP_WAIT(n)  asm volatile("cp.async.wait_group %0;\n" :: "n"(n) : "memory")

// ---------------------------------------------------------------------------
// Fused fp32 -> fp16 converter for u, W_in, W_out in ONE launch.
// ---------------------------------------------------------------------------
__global__ __launch_bounds__(256) void convert_all_kernel(
    const float* __restrict__ u,
    const float* __restrict__ W_in,
    const float* __restrict__ W_out)
{
    __half* u_h  = reinterpret_cast<__half*>(g_scratch + UH_OFF);
    __half* Wi_h = reinterpret_cast<__half*>(g_scratch + WIH_OFF);
    __half* Wo_h = reinterpret_cast<__half*>(g_scratch + WOH_OFF);

    const int total = (N_U + N_WI + N_WO) / 8;
    int idx = blockIdx.x * blockDim.x + threadIdx.x;
    int stride = gridDim.x * blockDim.x;

    for (; idx < total; idx += stride) {
        int i = idx * 8;
        const float* src;
        __half* dst;
        if (i < N_U)                { src = u + i;                dst = u_h + i; }
        else if (i < N_U + N_WI)    { src = W_in + (i - N_U);     dst = Wi_h + (i - N_U); }
        else                        { src = W_out + (i - N_U - N_WI); dst = Wo_h + (i - N_U - N_WI); }

        float4 v0 = *reinterpret_cast<const float4*>(src);
        float4 v1 = *reinterpret_cast<const float4*>(src + 4);
        __half2 h0 = __floats2half2_rn(v0.x, v0.y);
        __half2 h1 = __floats2half2_rn(v0.z, v0.w);
        __half2 h2 = __floats2half2_rn(v1.x, v1.y);
        __half2 h3 = __floats2half2_rn(v1.z, v1.w);
        uint4 pack;
        pack.x = *reinterpret_cast<unsigned int*>(&h0);
        pack.y = *reinterpret_cast<unsigned int*>(&h1);
        pack.z = *reinterpret_cast<unsigned int*>(&h2);
        pack.w = *reinterpret_cast<unsigned int*>(&h3);
        *reinterpret_cast<uint4*>(dst) = pack;
    }
}

// ---------------------------------------------------------------------------
// FP16 tensor-core NT GEMM (fp32 accumulate), cp.async 2-stage double buffer.
// EXACT R10 structure. Block 128x128, BK=32, 8 warps (2x4).
// ---------------------------------------------------------------------------
#define BKH 40

__global__ __launch_bounds__(256, 2) void hgemm_nt(
    int M, int N, int K,
    const __half* __restrict__ A,
    const __half* __restrict__ B,
    float* __restrict__ C)
{
    __shared__ __half As[2][128 * BKH];
    __shared__ __half Bs[2][128 * BKH];

    const int tid = threadIdx.x;
    const int wid = tid >> 5;
    const int m0 = blockIdx.y * 128;
    const int n0 = blockIdx.x * 128;
    const int wm = (wid & 1) * 64;
    const int wn = (wid >> 1) * 32;

    const int lrow = tid >> 2;
    const int lch  = (tid & 3) * 8;

    wmma::fragment<wmma::accumulator, 16, 16, 16, float> acc[4][2];
#pragma unroll
    for (int i = 0; i < 4; ++i)
#pragma unroll
        for (int j = 0; j < 2; ++j)
            wmma::fill_fragment(acc[i][j], 0.f);

    auto load_stage = [&](int s, int kt) {
#pragma unroll
        for (int i = 0; i < 2; ++i) {
            int row = i * 64 + lrow;
            cp_async16h(&As[s][row * BKH + lch],
                        A + (size_t)(m0 + row) * K + kt + lch, true);
            bool bp = (n0 + row) < N;
            cp_async16h(&Bs[s][row * BKH + lch],
                        B + (size_t)(n0 + row) * K + bp * ((size_t)kt + lch), bp);
        }
        CP_COMMIT();
    };

    const int nt = K >> 5;
    load_stage(0, 0);

    for (int it = 0; it < nt; ++it) {
        const int s = it & 1;
        if (it + 1 < nt) {
            load_stage(s ^ 1, (it + 1) << 5);
            CP_WAIT(1);
        } else {
            CP_WAIT(0);
        }
        __syncthreads();

        const __half* Asm = As[s];
        const __half* Bsm = Bs[s];
#pragma unroll
        for (int k16 = 0; k16 < 32; k16 += 16) {
            wmma::fragment<wmma::matrix_b, 16, 16, 16, __half, wmma::col_major> bf[2];
#pragma unroll
            for (int j = 0; j < 2; ++j)
                wmma::load_matrix_sync(bf[j], Bsm + (wn + j * 16) * BKH + k16, BKH);
#pragma unroll
            for (int i = 0; i < 4; ++i) {
                wmma::fragment<wmma::matrix_a, 16, 16, 16, __half, wmma::row_major> af;
                wmma::load_matrix_sync(af, Asm + (wm + i * 16) * BKH + k16, BKH);
                wmma::mma_sync(acc[i][0], af, bf[0], acc[i][0]);
                wmma::mma_sync(acc[i][1], af, bf[1], acc[i][1]);
            }
        }
        __syncthreads();
    }

#pragma unroll
    for (int i = 0; i < 4; ++i) {
#pragma unroll
        for (int j = 0; j < 2; ++j) {
            int cc = n0 + wn + j * 16;
            if (cc < N)
                wmma::store_matrix_sync(
                    C + (size_t)(m0 + wm + i * 16) * N + cc,
                    acc[i][j], N, wmma::mem_row_major);
        }
    }
}

// ---------------------------------------------------------------------------
// Prep: per (b,s) row of proj, compute a[b,s,h], gdtB[b,s,h,n], Cm[b,s,h,n]
// ---------------------------------------------------------------------------
__global__ __launch_bounds__(128) void prep_kernel(
    const float* __restrict__ dt_bias,
    const float* __restrict__ B_bias,
    const float* __restrict__ C_bias,
    const float* __restrict__ Bn_w,
    const float* __restrict__ Cn_w)
{
    const int bs = blockIdx.x;
    const int tid = threadIdx.x;
    const float* row = g_scratch + PROJ_OFF + (size_t)bs * KPROJ;

    __shared__ float normB[64], normC[64];
    __shared__ float cs[16], sn[16];
    __shared__ float gdt_s[64];
    __shared__ float red[4];

    float v = (tid < 64) ? row[OFF_B + tid] : row[OFF_C + (tid - 64)];
    float sq = v * v;
#pragma unroll
    for (int o = 16; o > 0; o >>= 1) sq += __shfl_xor_sync(0xffffffffu, sq, o);
    if ((tid & 31) == 0) red[tid >> 5] = sq;
    __syncthreads();
    float rB = rsqrtf((red[0] + red[1]) * (1.f / 64.f) + EPSV);
    float rC = rsqrtf((red[2] + red[3]) * (1.f / 64.f) + EPSV);
    if (tid < 64) normB[tid] = v * rB * Bn_w[tid];
    else          normC[tid - 64] = v * rC * Cn_w[tid - 64];

    if (tid < 64) {
        int h = tid;
        float dt = softplusf(row[OFF_DT + h] + dt_bias[h]);
        float A  = fminf(-softplusf(row[OFF_A + h]), -1e-4f);
        float trap = sigmoidf_(row[OFF_TR + h]);
        float g = 1.f - 0.5f * trap;
        float a = g * expf(A * dt) + 0.5f * trap;
        g_scratch[AARR_OFF + (size_t)bs * NH + h] = a;
        gdt_s[h] = g * dt;
    }
    if (tid < 16) {
        float ang = row[OFF_ANG + tid];
        cs[tid] = cosf(ang);
        sn[tid] = sinf(ang);
    }
    __syncthreads();

    float* gb_out = g_scratch + GB_OFF + (size_t)bs * (NH * DS);
    float* cm_out = g_scratch + CM_OFF + (size_t)bs * (NH * DS);
#pragma unroll
    for (int it = 0; it < 32; ++it) {
        int i = it * 128 + tid;
        int h = i >> 6;
        int n = i & 63;
        float vB = normB[n] + B_bias[i];
        float vC = normC[n] + C_bias[i];
        float oB, oC;
        if (n < 16) {
            float b2 = normB[n + 16] + B_bias[h * 64 + n + 16];
            float c2 = normC[n + 16] + C_bias[h * 64 + n + 16];
            oB = vB * cs[n] - b2 * sn[n];
            oC = vC * cs[n] - c2 * sn[n];
        } else if (n < 32) {
            int j = n - 16;
            float b1 = normB[j] + B_bias[h * 64 + j];
            float c1 = normC[j] + C_bias[h * 64 + j];
            oB = b1 * sn[j] + vB * cs[j];
            oC = c1 * sn[j] + vC * cs[j];
        } else {
            oB = vB;
            oC = vC;
        }
        gb_out[i] = gdt_s[h] * oB;
        cm_out[i] = oC;
    }
}

// ---------------------------------------------------------------------------
// Pass 1: local scan within each chunk (h0 = 0). Coefficients staged through
// a DEPTH-4 smem ring via cp.async (stage t+2 ahead, CP_WAIT(2)).
// Depth 4 makes the write target (t+2)%4 == (t-2)%4, whose readers ran at
// iteration t-2 and are separated from this write by two barriers: race-free.
// ---------------------------------------------------------------------------
__global__ __launch_bounds__(256) void scan_chunk_kernel(const float* __restrict__ Dv)
{
    const int bx = blockIdx.x;
    const int c = bx & (NC - 1);
    const int h = (bx >> 4) & (NH - 1);
    const int b = bx >> 10;
    const int tid = threadIdx.x;
    const int p = tid >> 3;
    const int ng = tid & 7;
    const int n0 = ng * 8;

    const float Dh = Dv[h];

    __shared__ __align__(16) float gb_s[4][64];
    __shared__ __align__(16) float cm_s[4][64];
    __shared__ __align__(16) float x_s[4][32];
    __shared__ float a_s[4];

    float hs0 = 0.f, hs1 = 0.f, hs2 = 0.f, hs3 = 0.f;
    float hs4 = 0.f, hs5 = 0.f, hs6 = 0.f, hs7 = 0.f;
    float P = 1.f;

    const float* proj = g_scratch + PROJ_OFF;
    const float* aarr = g_scratch + AARR_OFF;
    const float* gbb  = g_scratch + GB_OFF;
    const float* cmb  = g_scratch + CM_OFF;
    float* Yb = g_scratch + Y_OFF;
    float* Pb = g_scratch + PBUF_OFF;

    const int t0 = c * CHUNK;

    auto stage = [&](int s, int t) {
        const size_t bs = (size_t)b * SEQ + t;
        const size_t idx = bs * NH + h;
        if (tid < 16)
            cp_async16f(&gb_s[s][tid * 4], gbb + idx * DS + tid * 4);
        else if (tid < 32)
            cp_async16f(&cm_s[s][(tid - 16) * 4], cmb + idx * DS + (tid - 16) * 4);
        else if (tid < 40)
            cp_async16f(&x_s[s][(tid - 32) * 4],
                        proj + bs * KPROJ + OFF_X + h * HD + (tid - 32) * 4);
        else if (tid == 40)
            cp_async4f(&a_s[s], aarr + idx);
        CP_COMMIT();
    };

    stage(0, t0);
    stage(1, t0 + 1);

    for (int t = 0; t < CHUNK; ++t) {
        if (t + 2 < CHUNK) stage((t + 2) & 3, t0 + t + 2);
        else               CP_COMMIT();
        CP_WAIT(2);
        __syncthreads();

        const int s = t & 3;
        float a = a_s[s];
        float4 g0 = *reinterpret_cast<const float4*>(&gb_s[s][n0]);
        float4 g1 = *reinterpret_cast<const float4*>(&gb_s[s][n0 + 4]);
        float4 c0 = *reinterpret_cast<const float4*>(&cm_s[s][n0]);
        float4 c1 = *reinterpret_cast<const float4*>(&cm_s[s][n0 + 4]);
        float x = x_s[s][p];

        P *= a;

        hs0 = fmaf(a, hs0, x * g0.x);
        hs1 = fmaf(a, hs1, x * g0.y);
        hs2 = fmaf(a, hs2, x * g0.z);
        hs3 = fmaf(a, hs3, x * g0.w);
        hs4 = fmaf(a, hs4, x * g1.x);
        hs5 = fmaf(a, hs5, x * g1.y);
        hs6 = fmaf(a, hs6, x * g1.z);
        hs7 = fmaf(a, hs7, x * g1.w);

        float pa = fmaf(hs1, c0.y, hs0 * c0.x);
        float pb2 = fmaf(hs3, c0.w, hs2 * c0.z);
        float pc = fmaf(hs5, c1.y, hs4 * c1.x);
        float pd = fmaf(hs7, c1.w, hs6 * c1.z);
        float part = (pa + pb2) + (pc + pd);

        part += __shfl_down_sync(0xffffffffu, part, 4, 8);
        part += __shfl_down_sync(0xffffffffu, part, 2, 8);
        part += __shfl_down_sync(0xffffffffu, part, 1, 8);

        const size_t bs = (size_t)b * SEQ + t0 + t;
        if (ng == 0) {
            Yb[bs * DI + h * HD + p] = part + Dh * x;
        }
        if (tid == 0) {
            Pb[bs * NH + h] = P;
        }
    }

    float* hst = g_scratch + HST_OFF +
                 (((size_t)(b * NH + h) * NC + c) * (HD * DS)) + p * DS + n0;
    reinterpret_cast<float4*>(hst)[0] = make_float4(hs0, hs1, hs2, hs3);
    reinterpret_cast<float4*>(hst)[1] = make_float4(hs4, hs5, hs6, hs7);
}

// ---------------------------------------------------------------------------
// Pass 2: sequential combine of chunk states into prefix end-states.
// ---------------------------------------------------------------------------
__global__ __launch_bounds__(256) void combine_kernel()
{
    const int bh = blockIdx.x;
    const int b = bh >> 6;
    const int h = bh & 63;
    const int tid = threadIdx.x;
    const int e = tid * 8;

    float* base = g_scratch + HST_OFF + (size_t)bh * NC * (HD * DS);
    const float* Pb = g_scratch + PBUF_OFF;

    float4 H0 = reinterpret_cast<float4*>(base + e)[0];
    float4 H1 = reinterpret_cast<float4*>(base + e)[1];

    for (int c = 1; c < NC; ++c) {
        float Atot = Pb[((size_t)b * SEQ + c * CHUNK + CHUNK - 1) * NH + h];
        float* ptr = base + (size_t)c * (HD * DS) + e;
        float4 L0 = reinterpret_cast<float4*>(ptr)[0];
        float4 L1 = reinterpret_cast<float4*>(ptr)[1];
        H0.x = fmaf(Atot, H0.x, L0.x); H0.y = fmaf(Atot, H0.y, L0.y);
        H0.z = fmaf(Atot, H0.z, L0.z); H0.w = fmaf(Atot, H0.w, L0.w);
        H1.x = fmaf(Atot, H1.x, L1.x); H1.y = fmaf(Atot, H1.y, L1.y);
        H1.z = fmaf(Atot, H1.z, L1.z); H1.w = fmaf(Atot, H1.w, L1.w);
        reinterpret_cast<float4*>(ptr)[0] = H0;
        reinterpret_cast<float4*>(ptr)[1] = H1;
    }
}

// ---------------------------------------------------------------------------
// Pass 3: y += P_t * (C_t . H_prev), then * silu(z); write fp16 Y for GEMM2.
// cm row + P staged through DEPTH-4 smem ring (same race-free scheme).
// ---------------------------------------------------------------------------
__global__ __launch_bounds__(256) void fixup_kernel()
{
    const int bx = blockIdx.x;
    const int c = bx & (NC - 1);
    const int h = (bx >> 4) & (NH - 1);
    const int b = bx >> 10;
    const int tid = threadIdx.x;
    const int p = tid >> 3;
    const int ng = tid & 7;
    const int n0 = ng * 8;

    const float* proj = g_scratch + PROJ_OFF;
    const float* cmb  = g_scratch + CM_OFF;
    const float* Pb   = g_scratch + PBUF_OFF;
    const float* Yb   = g_scratch + Y_OFF;
    __half* Yh = reinterpret_cast<__half*>(g_scratch + YH_OFF);

    __shared__ __align__(16) float cm_s[4][64];
    __shared__ float P_s[4];

    float4 hp0 = make_float4(0.f, 0.f, 0.f, 0.f);
    float4 hp1 = make_float4(0.f, 0.f, 0.f, 0.f);
    if (c > 0) {
        const float* hst = g_scratch + HST_OFF +
            (((size_t)(b * NH + h) * NC + (c - 1)) * (HD * DS)) + p * DS + n0;
        hp0 = reinterpret_cast<const float4*>(hst)[0];
        hp1 = reinterpret_cast<const float4*>(hst)[1];
    }

    const int t0 = c * CHUNK;

    auto stage = [&](int s, int t) {
        const size_t bs = (size_t)b * SEQ + t;
        const size_t idx = bs * NH + h;
        if (tid < 16)
            cp_async16f(&cm_s[s][tid * 4], cmb + idx * DS + tid * 4);
        else if (tid == 16)
            cp_async4f(&P_s[s], Pb + idx);
        CP_COMMIT();
    };

    stage(0, t0);
    stage(1, t0 + 1);

    for (int t = 0; t < CHUNK; ++t) {
        if (t + 2 < CHUNK) stage((t + 2) & 3, t0 + t + 2);
        else               CP_COMMIT();
        CP_WAIT(2);
        __syncthreads();

        const int s = t & 3;
        float4 c0 = *reinterpret_cast<const float4*>(&cm_s[s][n0]);
        float4 c1 = *reinterpret_cast<const float4*>(&cm_s[s][n0 + 4]);

        float pa = fmaf(hp0.y, c0.y, hp0.x * c0.x);
        float pb2 = fmaf(hp0.w, c0.w, hp0.z * c0.z);
        float pc = fmaf(hp1.y, c1.y, hp1.x * c1.x);
        float pd = fmaf(hp1.w, c1.w, hp1.z * c1.z);
        float part = (pa + pb2) + (pc + pd);

        part += __shfl_down_sync(0xffffffffu, part, 4, 8);
        part += __shfl_down_sync(0xffffffffu, part, 2, 8);
        part += __shfl_down_sync(0xffffffffu, part, 1, 8);

        if (ng == 0) {
            const size_t bs = (size_t)b * SEQ + t0 + t;
            float y = Yb[bs * DI + h * HD + p];
            if (c > 0) {
                y = fmaf(P_s[s], part, y);
            }
            float z = proj[bs * KPROJ + OFF_Z + h * HD + p];
            float silu = z * sigmoidf_(z);
            Yh[bs * DI + h * HD + p] = __float2half_rn(y * silu);
        }
    }
}

// ---------------------------------------------------------------------------
extern "C" void kernel_launch(void* const* d_in, const int* in_sizes, int n_in,
                              void* d_out, int out_size)
{
    const float* u       = (const float*)d_in[0];
    const float* W_in    = (const float*)d_in[1];
    const float* dt_bias = (const float*)d_in[2];
    const float* B_bias  = (const float*)d_in[3];
    const float* C_bias  = (const float*)d_in[4];
    const float* Bn_w    = (const float*)d_in[5];
    const float* Cn_w    = (const float*)d_in[6];
    const float* Dv      = (const float*)d_in[7];
    const float* W_out   = (const float*)d_in[8];
    float* out = (float*)d_out;

    float* scratch = nullptr;
    cudaGetSymbolAddress((void**)&scratch, g_scratch);

    float* proj = scratch + PROJ_OFF;
    __half* u_h  = reinterpret_cast<__half*>(scratch + UH_OFF);
    __half* Wi_h = reinterpret_cast<__half*>(scratch + WIH_OFF);
    __half* Wo_h = reinterpret_cast<__half*>(scratch + WOH_OFF);
    __half* Yh   = reinterpret_cast<__half*>(scratch + YH_OFF);

    // Convert all GEMM operands to fp16 in ONE launch
    convert_all_kernel<<<888, 256>>>(u, W_in, W_out);

    // GEMM1: proj[BSTOT, KPROJ] = u @ W_in^T  (fp16 in, fp32 accum)
    {
        dim3 grid((KPROJ + 127) / 128, BSTOT / 128);
        hgemm_nt<<<grid, 256>>>(BSTOT, KPROJ, DM, u_h, Wi_h, proj);
    }

    prep_kernel<<<BSTOT, 128>>>(dt_bias, B_bias, C_bias, Bn_w, Cn_w);

    // chunked scan
    scan_chunk_kernel<<<NBATCH * NH * NC, 256>>>(Dv);
    combine_kernel<<<NBATCH * NH, 256>>>();
    fixup_kernel<<<NBATCH * NH * NC, 256>>>();

    // GEMM2: out[BSTOT, DM] = Y @ W_out^T  (fp16 in, fp32 accum)
    {
        dim3 grid(DM / 128, BSTOT / 128);
        hgemm_nt<<<grid, 256>>>(BSTOT, DM, DI, Yh, Wo_h, out);
    }
}

// round 16
// speedup vs baseline: 1.8692x; 1.8692x over previous
#include <cuda_runtime.h>
#include <cuda_fp16.h>
#include <cstdint>
#include <math.h>
#include <mma.h>

using namespace nvcuda;

#define SEQ    1024
#define NBATCH 2
#define BSTOT  2048      // B*S
#define NH     64
#define HD     32
#define DS     64
#define KPROJ  4432
#define DI     2048
#define DM     1024
#define EPSV   1e-5f

#define CHUNK  64
#define NC     16        // SEQ / CHUNK

// offsets inside one proj row of length KPROJ
#define OFF_Z   0
#define OFF_X   2048
#define OFF_B   4096
#define OFF_C   4160
#define OFF_DT  4224
#define OFF_A   4288
#define OFF_TR  4352
#define OFF_ANG 4416

// scratch layout (float units)
#define PROJ_OFF 0ull
#define AARR_OFF 9076736ull      // + BSTOT*KPROJ
#define GB_OFF   9207808ull      // + BSTOT*NH
#define CM_OFF   17596416ull     // + BSTOT*NH*DS
#define Y_OFF    25985024ull     // + BSTOT*NH*DS
#define HST_OFF  30179328ull     // + BSTOT*DI
#define PBUF_OFF 34373632ull     // + NBATCH*NH*NC*HD*DS
#define UH_OFF   34504704ull     // + BSTOT*NH            : half copy of u
#define WIH_OFF  35553280ull     // + BSTOT*DM/2          : half copy of W_in
#define WOH_OFF  37822464ull     // + KPROJ*DM/2          : half copy of W_out
#define YH_OFF   38871040ull     // + DM*DI/2             : half copy of Y
#define SCRATCH_TOTAL 40968192ull

// converter segment sizes (elements)
#define N_U  (BSTOT * DM)
#define N_WI (KPROJ * DM)
#define N_WO (DM * DI)

__device__ __align__(16) float g_scratch[SCRATCH_TOTAL];

__device__ __forceinline__ float softplusf(float x) {
    return x > 20.f ? x : log1pf(expf(x));
}
__device__ __forceinline__ float sigmoidf_(float x) {
    return 1.f / (1.f + expf(-x));
}

__device__ __forceinline__ void cp_async16h(__half* smem_dst, const __half* gsrc, bool pred) {
    unsigned int saddr = (unsigned int)__cvta_generic_to_shared(smem_dst);
    int sz = pred ? 16 : 0;
    asm volatile("cp.async.cg.shared.global [%0], [%1], 16, %2;\n"
                 :: "r"(saddr), "l"(gsrc), "r"(sz));
}
#define CP_COMMIT() asm volatile("cp.async.commit_group;\n" ::: "memory")
#define CP_WAIT(n)  asm volatile("cp.async.wait_group %0;\n" :: "n"(n) : "memory")

// split a float into hi/lo halves (v ~= hi + lo, ~22-bit effective precision)
__device__ __forceinline__ void split1(__half* hi, __half* lo, int off, float v) {
    __half h = __float2half_rn(v);
    hi[off] = h;
    lo[off] = __float2half_rn(v - __half2float(h));
}
__device__ __forceinline__ void split4(__half* hi, __half* lo, int off, float4 v) {
    split1(hi, lo, off + 0, v.x);
    split1(hi, lo, off + 1, v.y);
    split1(hi, lo, off + 2, v.z);
    split1(hi, lo, off + 3, v.w);
}

// ---------------------------------------------------------------------------
// Fused fp32 -> fp16 converter for u, W_in, W_out in ONE launch.
// ---------------------------------------------------------------------------
__global__ __launch_bounds__(256) void convert_all_kernel(
    const float* __restrict__ u,
    const float* __restrict__ W_in,
    const float* __restrict__ W_out)
{
    __half* u_h  = reinterpret_cast<__half*>(g_scratch + UH_OFF);
    __half* Wi_h = reinterpret_cast<__half*>(g_scratch + WIH_OFF);
    __half* Wo_h = reinterpret_cast<__half*>(g_scratch + WOH_OFF);

    const int total = (N_U + N_WI + N_WO) / 8;
    int idx = blockIdx.x * blockDim.x + threadIdx.x;
    int stride = gridDim.x * blockDim.x;

    for (; idx < total; idx += stride) {
        int i = idx * 8;
        const float* src;
        __half* dst;
        if (i < N_U)                { src = u + i;                dst = u_h + i; }
        else if (i < N_U + N_WI)    { src = W_in + (i - N_U);     dst = Wi_h + (i - N_U); }
        else                        { src = W_out + (i - N_U - N_WI); dst = Wo_h + (i - N_U - N_WI); }

        float4 v0 = *reinterpret_cast<const float4*>(src);
        float4 v1 = *reinterpret_cast<const float4*>(src + 4);
        __half2 h0 = __floats2half2_rn(v0.x, v0.y);
        __half2 h1 = __floats2half2_rn(v0.z, v0.w);
        __half2 h2 = __floats2half2_rn(v1.x, v1.y);
        __half2 h3 = __floats2half2_rn(v1.z, v1.w);
        uint4 pack;
        pack.x = *reinterpret_cast<unsigned int*>(&h0);
        pack.y = *reinterpret_cast<unsigned int*>(&h1);
        pack.z = *reinterpret_cast<unsigned int*>(&h2);
        pack.w = *reinterpret_cast<unsigned int*>(&h3);
        *reinterpret_cast<uint4*>(dst) = pack;
    }
}

// ---------------------------------------------------------------------------
// FP16 tensor-core NT GEMM (fp32 accumulate), cp.async 2-stage double buffer.
// ---------------------------------------------------------------------------
#define BKH 40

__global__ __launch_bounds__(256, 2) void hgemm_nt(
    int M, int N, int K,
    const __half* __restrict__ A,
    const __half* __restrict__ B,
    float* __restrict__ C)
{
    __shared__ __half As[2][128 * BKH];
    __shared__ __half Bs[2][128 * BKH];

    const int tid = threadIdx.x;
    const int wid = tid >> 5;
    const int m0 = blockIdx.y * 128;
    const int n0 = blockIdx.x * 128;
    const int wm = (wid & 1) * 64;
    const int wn = (wid >> 1) * 32;

    const int lrow = tid >> 2;
    const int lch  = (tid & 3) * 8;

    wmma::fragment<wmma::accumulator, 16, 16, 16, float> acc[4][2];
#pragma unroll
    for (int i = 0; i < 4; ++i)
#pragma unroll
        for (int j = 0; j < 2; ++j)
            wmma::fill_fragment(acc[i][j], 0.f);

    auto load_stage = [&](int s, int kt) {
#pragma unroll
        for (int i = 0; i < 2; ++i) {
            int row = i * 64 + lrow;
            cp_async16h(&As[s][row * BKH + lch],
                        A + (size_t)(m0 + row) * K + kt + lch, true);
            bool bp = (n0 + row) < N;
            cp_async16h(&Bs[s][row * BKH + lch],
                        B + (size_t)(n0 + row) * K + bp * ((size_t)kt + lch), bp);
        }
        CP_COMMIT();
    };

    const int nt = K >> 5;
    load_stage(0, 0);

    for (int it = 0; it < nt; ++it) {
        const int s = it & 1;
        if (it + 1 < nt) {
            load_stage(s ^ 1, (it + 1) << 5);
            CP_WAIT(1);
        } else {
            CP_WAIT(0);
        }
        __syncthreads();

        const __half* Asm = As[s];
        const __half* Bsm = Bs[s];
#pragma unroll
        for (int k16 = 0; k16 < 32; k16 += 16) {
            wmma::fragment<wmma::matrix_b, 16, 16, 16, __half, wmma::col_major> bf[2];
#pragma unroll
            for (int j = 0; j < 2; ++j)
                wmma::load_matrix_sync(bf[j], Bsm + (wn + j * 16) * BKH + k16, BKH);
#pragma unroll
            for (int i = 0; i < 4; ++i) {
                wmma::fragment<wmma::matrix_a, 16, 16, 16, __half, wmma::row_major> af;
                wmma::load_matrix_sync(af, Asm + (wm + i * 16) * BKH + k16, BKH);
                wmma::mma_sync(acc[i][0], af, bf[0], acc[i][0]);
                wmma::mma_sync(acc[i][1], af, bf[1], acc[i][1]);
            }
        }
        __syncthreads();
    }

#pragma unroll
    for (int i = 0; i < 4; ++i) {
#pragma unroll
        for (int j = 0; j < 2; ++j) {
            int cc = n0 + wn + j * 16;
            if (cc < N)
                wmma::store_matrix_sync(
                    C + (size_t)(m0 + wm + i * 16) * N + cc,
                    acc[i][j], N, wmma::mem_row_major);
        }
    }
}

// ---------------------------------------------------------------------------
// Prep (unchanged)
// ---------------------------------------------------------------------------
__global__ __launch_bounds__(128) void prep_kernel(
    const float* __restrict__ dt_bias,
    const float* __restrict__ B_bias,
    const float* __restrict__ C_bias,
    const float* __restrict__ Bn_w,
    const float* __restrict__ Cn_w)
{
    const int bs = blockIdx.x;
    const int tid = threadIdx.x;
    const float* row = g_scratch + PROJ_OFF + (size_t)bs * KPROJ;

    __shared__ float normB[64], normC[64];
    __shared__ float cs[16], sn[16];
    __shared__ float gdt_s[64];
    __shared__ float red[4];

    float v = (tid < 64) ? row[OFF_B + tid] : row[OFF_C + (tid - 64)];
    float sq = v * v;
#pragma unroll
    for (int o = 16; o > 0; o >>= 1) sq += __shfl_xor_sync(0xffffffffu, sq, o);
    if ((tid & 31) == 0) red[tid >> 5] = sq;
    __syncthreads();
    float rB = rsqrtf((red[0] + red[1]) * (1.f / 64.f) + EPSV);
    float rC = rsqrtf((red[2] + red[3]) * (1.f / 64.f) + EPSV);
    if (tid < 64) normB[tid] = v * rB * Bn_w[tid];
    else          normC[tid - 64] = v * rC * Cn_w[tid - 64];

    if (tid < 64) {
        int h = tid;
        float dt = softplusf(row[OFF_DT + h] + dt_bias[h]);
        float A  = fminf(-softplusf(row[OFF_A + h]), -1e-4f);
        float trap = sigmoidf_(row[OFF_TR + h]);
        float g = 1.f - 0.5f * trap;
        float a = g * expf(A * dt) + 0.5f * trap;
        g_scratch[AARR_OFF + (size_t)bs * NH + h] = a;
        gdt_s[h] = g * dt;
    }
    if (tid < 16) {
        float ang = row[OFF_ANG + tid];
        cs[tid] = cosf(ang);
        sn[tid] = sinf(ang);
    }
    __syncthreads();

    float* gb_out = g_scratch + GB_OFF + (size_t)bs * (NH * DS);
    float* cm_out = g_scratch + CM_OFF + (size_t)bs * (NH * DS);
#pragma unroll
    for (int it = 0; it < 32; ++it) {
        int i = it * 128 + tid;
        int h = i >> 6;
        int n = i & 63;
        float vB = normB[n] + B_bias[i];
        float vC = normC[n] + C_bias[i];
        float oB, oC;
        if (n < 16) {
            float b2 = normB[n + 16] + B_bias[h * 64 + n + 16];
            float c2 = normC[n + 16] + C_bias[h * 64 + n + 16];
            oB = vB * cs[n] - b2 * sn[n];
            oC = vC * cs[n] - c2 * sn[n];
        } else if (n < 32) {
            int j = n - 16;
            float b1 = normB[j] + B_bias[h * 64 + j];
            float c1 = normC[j] + C_bias[h * 64 + j];
            oB = b1 * sn[j] + vB * cs[j];
            oC = c1 * sn[j] + vC * cs[j];
        } else {
            oB = vB;
            oC = vC;
        }
        gb_out[i] = gdt_s[h] * oB;
        cm_out[i] = oC;
    }
}

// ---------------------------------------------------------------------------
// Pass 1 (SSD form): per (b,h,c) block, tensor-core intra-chunk computation.
//   G = C @ gdtB^T;  M[t,s] = G * exp2(lp[t]-lp[s]) (s<=t);
//   Yloc = M @ X  -> Yb (fp32, raw);  Hend = X^T @ (gdtB * w_s) -> HST;
//   Pb[t] = exp2(lp[t]).
// fp16 operands with hi/lo split (3-term mma) => ~fp32-level accuracy.
// ---------------------------------------------------------------------------
#define LDT 72   // fp16 tile ld (64x64 tiles)
#define LDX 40   // fp16 tile ld (64x32 tiles)
#define LDG 68   // fp32 G buffer ld

#define SCAN_SMEM_BYTES ((64*LDG + 128) * 4 + (4 * 64*LDT + 2 * 64*LDX + 2 * 64*LDT) * 2)

__global__ __launch_bounds__(256) void scan_chunk_mma(const float* __restrict__ Dv)
{
    extern __shared__ char dsm[];
    float* Gf = reinterpret_cast<float*>(dsm);           // 64*68
    float* af = Gf + 64 * LDG;                           // 64
    float* lp = af + 64;                                 // 64
    __half* Ch = reinterpret_cast<__half*>(lp + 64);
    __half* Cl = Ch + 64 * LDT;
    __half* Bh = Cl + 64 * LDT;
    __half* Bl = Bh + 64 * LDT;
    __half* Xh = Bl + 64 * LDT;
    __half* Xl = Xh + 64 * LDX;
    __half* Mh = Xl + 64 * LDX;
    __half* Ml = Mh + 64 * LDT;

    const int bx = blockIdx.x;
    const int c = bx & (NC - 1);
    const int h = (bx >> 4) & (NH - 1);
    const int b = bx >> 10;
    const int tid = threadIdx.x;
    const int w = tid >> 5;
    const int t0 = c * CHUNK;

    const float* proj = g_scratch + PROJ_OFF;
    const float* aarr = g_scratch + AARR_OFF;
    const float* gbb  = g_scratch + GB_OFF;
    const float* cmb  = g_scratch + CM_OFF;
    float* Yb = g_scratch + Y_OFF;
    float* Pb = g_scratch + PBUF_OFF;

    // ---- load C, gdtB (64x64) and X (64x32), split hi/lo
    const size_t rowstride = (size_t)NH * DS;
    const float* cbase = cmb + ((size_t)(b * SEQ + t0) * NH + h) * DS;
    const float* bbase = gbb + ((size_t)(b * SEQ + t0) * NH + h) * DS;
    for (int i = tid; i < 1024; i += 256) {
        int r = i >> 4, c4 = (i & 15) << 2;
        float4 v = *reinterpret_cast<const float4*>(cbase + (size_t)r * rowstride + c4);
        split4(Ch, Cl, r * LDT + c4, v);
        float4 u = *reinterpret_cast<const float4*>(bbase + (size_t)r * rowstride + c4);
        split4(Bh, Bl, r * LDT + c4, u);
    }
    const float* xbase = proj + (size_t)(b * SEQ + t0) * KPROJ + OFF_X + h * HD;
    for (int i = tid; i < 512; i += 256) {
        int r = i >> 3, c4 = (i & 7) << 2;
        float4 v = *reinterpret_cast<const float4*>(xbase + (size_t)r * KPROJ + c4);
        split4(Xh, Xl, r * LDX + c4, v);
    }
    if (tid < 64) af[tid] = aarr[((size_t)(b * SEQ + t0 + tid)) * NH + h];
    __syncthreads();

    // ---- log-space cumulative decay
    if (tid < 64) af[tid] = log2f(fmaxf(af[tid], 1e-37f));
    __syncthreads();
    if (tid == 0) {
        float L = 0.f;
        for (int t = 0; t < CHUNK; ++t) { L += af[t]; lp[t] = L; }
    }
    __syncthreads();
    if (tid < 64) Pb[((size_t)(b * SEQ + t0 + tid)) * NH + h] = exp2f(lp[tid]);

    // ---- G = C @ gdtB^T  (64x64x64), hi/lo 3-term
    {
        const int tr = w & 3;
        const int tcb = (w >> 2) * 2;
        wmma::fragment<wmma::accumulator, 16, 16, 16, float> acc[2];
        wmma::fill_fragment(acc[0], 0.f);
        wmma::fill_fragment(acc[1], 0.f);
#pragma unroll
        for (int ks = 0; ks < 64; ks += 16) {
            wmma::fragment<wmma::matrix_a, 16, 16, 16, __half, wmma::row_major> ah, al;
            wmma::load_matrix_sync(ah, Ch + tr * 16 * LDT + ks, LDT);
            wmma::load_matrix_sync(al, Cl + tr * 16 * LDT + ks, LDT);
#pragma unroll
            for (int j = 0; j < 2; ++j) {
                wmma::fragment<wmma::matrix_b, 16, 16, 16, __half, wmma::col_major> bhf, blf;
                wmma::load_matrix_sync(bhf, Bh + (tcb + j) * 16 * LDT + ks, LDT);
                wmma::load_matrix_sync(blf, Bl + (tcb + j) * 16 * LDT + ks, LDT);
                wmma::mma_sync(acc[j], ah, bhf, acc[j]);
                wmma::mma_sync(acc[j], ah, blf, acc[j]);
                wmma::mma_sync(acc[j], al, bhf, acc[j]);
            }
        }
        wmma::store_matrix_sync(Gf + tr * 16 * LDG + tcb * 16, acc[0], LDG, wmma::mem_row_major);
        wmma::store_matrix_sync(Gf + tr * 16 * LDG + (tcb + 1) * 16, acc[1], LDG, wmma::mem_row_major);
    }
    __syncthreads();

    // ---- build masked M, and rescale B rows by w_s = exp2(lp[63]-lp[s])
    const float lpe = lp[63];
    for (int i = tid; i < 4096; i += 256) {
        int t = i >> 6, s = i & 63;
        float g = (s <= t) ? Gf[t * LDG + s] * exp2f(lp[t] - lp[s]) : 0.f;
        split1(Mh, Ml, t * LDT + s, g);
    }
    for (int i = tid; i < 4096; i += 256) {
        int s = i >> 6, n = i & 63;
        int off = s * LDT + n;
        float bv = __half2float(Bh[off]) + __half2float(Bl[off]);
        bv *= exp2f(lpe - lp[s]);
        split1(Bh, Bl, off, bv);
    }
    __syncthreads();

    // ---- Yloc = M @ X (64x32x64) -> global Yb ; Hend = X^T @ Bscaled -> HST
    {
        const int tr = w & 3;
        const int tc = w >> 2;          // 0..1
        wmma::fragment<wmma::accumulator, 16, 16, 16, float> accY;
        wmma::fill_fragment(accY, 0.f);
#pragma unroll
        for (int ks = 0; ks < 64; ks += 16) {
            wmma::fragment<wmma::matrix_a, 16, 16, 16, __half, wmma::row_major> ah, al;
            wmma::load_matrix_sync(ah, Mh + tr * 16 * LDT + ks, LDT);
            wmma::load_matrix_sync(al, Ml + tr * 16 * LDT + ks, LDT);
            wmma::fragment<wmma::matrix_b, 16, 16, 16, __half, wmma::row_major> bhf, blf;
            wmma::load_matrix_sync(bhf, Xh + ks * LDX + tc * 16, LDX);
            wmma::load_matrix_sync(blf, Xl + ks * LDX + tc * 16, LDX);
            wmma::mma_sync(accY, ah, bhf, accY);
            wmma::mma_sync(accY, ah, blf, accY);
            wmma::mma_sync(accY, al, bhf, accY);
        }
        float* yp = Yb + (size_t)(b * SEQ + t0 + tr * 16) * DI + h * HD + tc * 16;
        wmma::store_matrix_sync(yp, accY, DI, wmma::mem_row_major);

        const int pr = w & 1;           // 0..1 (p)
        const int nc = w >> 1;          // 0..3 (n)
        wmma::fragment<wmma::accumulator, 16, 16, 16, float> accH;
        wmma::fill_fragment(accH, 0.f);
#pragma unroll
        for (int ks = 0; ks < 64; ks += 16) {
            wmma::fragment<wmma::matrix_a, 16, 16, 16, __half, wmma::col_major> ah, al;
            wmma::load_matrix_sync(ah, Xh + pr * 16 + ks * LDX, LDX);
            wmma::load_matrix_sync(al, Xl + pr * 16 + ks * LDX, LDX);
            wmma::fragment<wmma::matrix_b, 16, 16, 16, __half, wmma::row_major> bhf, blf;
            wmma::load_matrix_sync(bhf, Bh + ks * LDT + nc * 16, LDT);
            wmma::load_matrix_sync(blf, Bl + ks * LDT + nc * 16, LDT);
            wmma::mma_sync(accH, ah, bhf, accH);
            wmma::mma_sync(accH, ah, blf, accH);
            wmma::mma_sync(accH, al, bhf, accH);
        }
        float* hp = g_scratch + HST_OFF +
                    (((size_t)(b * NH + h) * NC + c) * (HD * DS)) + (pr * 16) * DS + nc * 16;
        wmma::store_matrix_sync(hp, accH, DS, wmma::mem_row_major);
    }
}

// ---------------------------------------------------------------------------
// Pass 2: sequential combine of chunk states into prefix end-states.
// ---------------------------------------------------------------------------
__global__ __launch_bounds__(256) void combine_kernel()
{
    const int bh = blockIdx.x;
    const int b = bh >> 6;
    const int h = bh & 63;
    const int tid = threadIdx.x;
    const int e = tid * 8;

    float* base = g_scratch + HST_OFF + (size_t)bh * NC * (HD * DS);
    const float* Pb = g_scratch + PBUF_OFF;

    float4 H0 = reinterpret_cast<float4*>(base + e)[0];
    float4 H1 = reinterpret_cast<float4*>(base + e)[1];

    for (int c = 1; c < NC; ++c) {
        float Atot = Pb[((size_t)b * SEQ + c * CHUNK + CHUNK - 1) * NH + h];
        float* ptr = base + (size_t)c * (HD * DS) + e;
        float4 L0 = reinterpret_cast<float4*>(ptr)[0];
        float4 L1 = reinterpret_cast<float4*>(ptr)[1];
        H0.x = fmaf(Atot, H0.x, L0.x); H0.y = fmaf(Atot, H0.y, L0.y);
        H0.z = fmaf(Atot, H0.z, L0.z); H0.w = fmaf(Atot, H0.w, L0.w);
        H1.x = fmaf(Atot, H1.x, L1.x); H1.y = fmaf(Atot, H1.y, L1.y);
        H1.z = fmaf(Atot, H1.z, L1.z); H1.w = fmaf(Atot, H1.w, L1.w);
        reinterpret_cast<float4*>(ptr)[0] = H0;
        reinterpret_cast<float4*>(ptr)[1] = H1;
    }
}

// ---------------------------------------------------------------------------
// Pass 3 (SSD form): Ycorr = C @ Hprev (64x32x64 tensor core);
// y = (Yloc + P[t]*Ycorr + Dh*x) * silu(z) -> fp16 Yh.
// ---------------------------------------------------------------------------
__global__ __launch_bounds__(256) void fixup_mma(const float* __restrict__ Dv)
{
    __shared__ __half Ch[64 * LDT];
    __shared__ __half Cl[64 * LDT];
    __shared__ __half Hh[32 * LDT];   // col_major buf[n + p*LDT]
    __shared__ __half Hl[32 * LDT];
    __shared__ float Yc[64 * LDX];
    __shared__ float Pf[64];

    const int bx = blockIdx.x;
    const int c = bx & (NC - 1);
    const int h = (bx >> 4) & (NH - 1);
    const int b = bx >> 10;
    const int tid = threadIdx.x;
    const int w = tid >> 5;
    const int t0 = c * CHUNK;

    const float* proj = g_scratch + PROJ_OFF;
    const float* cmb  = g_scratch + CM_OFF;
    const float* Pb   = g_scratch + PBUF_OFF;
    const float* Yb   = g_scratch + Y_OFF;
    __half* Yh = reinterpret_cast<__half*>(g_scratch + YH_OFF);

    const float Dh = Dv[h];

    const size_t rowstride = (size_t)NH * DS;
    const float* cbase = cmb + ((size_t)(b * SEQ + t0) * NH + h) * DS;
    for (int i = tid; i < 1024; i += 256) {
        int r = i >> 4, c4 = (i & 15) << 2;
        float4 v = *reinterpret_cast<const float4*>(cbase + (size_t)r * rowstride + c4);
        split4(Ch, Cl, r * LDT + c4, v);
    }
    if (c > 0) {
        const float* hstp = g_scratch + HST_OFF +
            (((size_t)(b * NH + h) * NC + (c - 1)) * (HD * DS));
        for (int i = tid; i < 512; i += 256) {
            int r = i >> 4, c4 = (i & 15) << 2;   // r = p, c4 = n
            float4 v = *reinterpret_cast<const float4*>(hstp + r * DS + c4);
            split4(Hh, Hl, r * LDT + c4, v);
        }
    } else {
        for (int i = tid; i < 32 * LDT; i += 256) { Hh[i] = __float2half(0.f); Hl[i] = __float2half(0.f); }
    }
    if (tid < 64) Pf[tid] = Pb[((size_t)(b * SEQ + t0 + tid)) * NH + h];
    __syncthreads();

    // Ycorr = C @ Hprev : A row_major (t,n); B col_major buf[n + p*LDT]
    {
        const int tr = w & 3;
        const int tc = w >> 2;   // 0..1
        wmma::fragment<wmma::accumulator, 16, 16, 16, float> acc;
        wmma::fill_fragment(acc, 0.f);
#pragma unroll
        for (int ks = 0; ks < 64; ks += 16) {
            wmma::fragment<wmma::matrix_a, 16, 16, 16, __half, wmma::row_major> ah, al;
            wmma::load_matrix_sync(ah, Ch + tr * 16 * LDT + ks, LDT);
            wmma::load_matrix_sync(al, Cl + tr * 16 * LDT + ks, LDT);
            wmma::fragment<wmma::matrix_b, 16, 16, 16, __half, wmma::col_major> bhf, blf;
            wmma::load_matrix_sync(bhf, Hh + ks + (tc * 16) * LDT, LDT);
            wmma::load_matrix_sync(blf, Hl + ks + (tc * 16) * LDT, LDT);
            wmma::mma_sync(acc, ah, bhf, acc);
            wmma::mma_sync(acc, ah, blf, acc);
            wmma::mma_sync(acc, al, bhf, acc);
        }
        wmma::store_matrix_sync(Yc + tr * 16 * LDX + tc * 16, acc, LDX, wmma::mem_row_major);
    }
    __syncthreads();

    // epilogue: 8 elems per thread: t = tid/4, p0 = (tid%4)*8
    {
        const int t = tid >> 2;
        const int p0 = (tid & 3) << 3;
        const size_t bs = (size_t)b * SEQ + t0 + t;
        const float* yrow = Yb + bs * DI + h * HD + p0;
        const float* xrow = proj + bs * KPROJ + OFF_X + h * HD + p0;
        const float* zrow = proj + bs * KPROJ + OFF_Z + h * HD + p0;
        const float Pt = Pf[t];
        float r[8];
#pragma unroll
        for (int k = 0; k < 8; ++k) {
            float y = yrow[k] + Pt * Yc[t * LDX + p0 + k] + Dh * xrow[k];
            float z = zrow[k];
            r[k] = y * (z * sigmoidf_(z));
        }
        __half2 o0 = __floats2half2_rn(r[0], r[1]);
        __half2 o1 = __floats2half2_rn(r[2], r[3]);
        __half2 o2 = __floats2half2_rn(r[4], r[5]);
        __half2 o3 = __floats2half2_rn(r[6], r[7]);
        uint4 pack;
        pack.x = *reinterpret_cast<unsigned int*>(&o0);
        pack.y = *reinterpret_cast<unsigned int*>(&o1);
        pack.z = *reinterpret_cast<unsigned int*>(&o2);
        pack.w = *reinterpret_cast<unsigned int*>(&o3);
        *reinterpret_cast<uint4*>(Yh + bs * DI + h * HD + p0) = pack;
    }
}

// ---------------------------------------------------------------------------
extern "C" void kernel_launch(void* const* d_in, const int* in_sizes, int n_in,
                              void* d_out, int out_size)
{
    const float* u       = (const float*)d_in[0];
    const float* W_in    = (const float*)d_in[1];
    const float* dt_bias = (const float*)d_in[2];
    const float* B_bias  = (const float*)d_in[3];
    const float* C_bias  = (const float*)d_in[4];
    const float* Bn_w    = (const float*)d_in[5];
    const float* Cn_w    = (const float*)d_in[6];
    const float* Dv      = (const float*)d_in[7];
    const float* W_out   = (const float*)d_in[8];
    float* out = (float*)d_out;

    float* scratch = nullptr;
    cudaGetSymbolAddress((void**)&scratch, g_scratch);

    float* proj = scratch + PROJ_OFF;
    __half* u_h  = reinterpret_cast<__half*>(scratch + UH_OFF);
    __half* Wi_h = reinterpret_cast<__half*>(scratch + WIH_OFF);
    __half* Wo_h = reinterpret_cast<__half*>(scratch + WOH_OFF);
    __half* Yh   = reinterpret_cast<__half*>(scratch + YH_OFF);

    cudaFuncSetAttribute(scan_chunk_mma,
        cudaFuncAttributeMaxDynamicSharedMemorySize, SCAN_SMEM_BYTES);

    // Convert all GEMM operands to fp16 in ONE launch
    convert_all_kernel<<<888, 256>>>(u, W_in, W_out);

    // GEMM1: proj = u @ W_in^T
    {
        dim3 grid((KPROJ + 127) / 128, BSTOT / 128);
        hgemm_nt<<<grid, 256>>>(BSTOT, KPROJ, DM, u_h, Wi_h, proj);
    }

    prep_kernel<<<BSTOT, 128>>>(dt_bias, B_bias, C_bias, Bn_w, Cn_w);

    // chunked scan (SSD matrix form)
    scan_chunk_mma<<<NBATCH * NH * NC, 256, SCAN_SMEM_BYTES>>>(Dv);
    combine_kernel<<<NBATCH * NH, 256>>>();
    fixup_mma<<<NBATCH * NH * NC, 256>>>(Dv);

    // GEMM2: out = Y @ W_out^T
    {
        dim3 grid(DM / 128, BSTOT / 128);
        hgemm_nt<<<grid, 256>>>(BSTOT, DM, DI, Yh, Wo_h, out);
    }
}

// round 17
// speedup vs baseline: 1.9683x; 1.0530x over previous
#include <cuda_runtime.h>
#include <cuda_fp16.h>
#include <cstdint>
#include <math.h>
#include <mma.h>

using namespace nvcuda;

#define SEQ    1024
#define NBATCH 2
#define BSTOT  2048      // B*S
#define NH     64
#define HD     32
#define DS     64
#define KPROJ  4432
#define DI     2048
#define DM     1024
#define EPSV   1e-5f

#define CHUNK  64
#define NC     16        // SEQ / CHUNK

// offsets inside one proj row of length KPROJ
#define OFF_Z   0
#define OFF_X   2048
#define OFF_B   4096
#define OFF_C   4160
#define OFF_DT  4224
#define OFF_A   4288
#define OFF_TR  4352
#define OFF_ANG 4416

// scratch layout (float units)
#define PROJ_OFF 0ull
#define AARR_OFF 9076736ull      // + BSTOT*KPROJ
#define GB_OFF   9207808ull      // + BSTOT*NH
#define CM_OFF   17596416ull     // + BSTOT*NH*DS
#define Y_OFF    25985024ull     // + BSTOT*NH*DS
#define HST_OFF  30179328ull     // + BSTOT*DI
#define PBUF_OFF 34373632ull     // + NBATCH*NH*NC*HD*DS
#define UH_OFF   34504704ull     // + BSTOT*NH            : half copy of u
#define WIH_OFF  35553280ull     // + BSTOT*DM/2          : half copy of W_in
#define WOH_OFF  37822464ull     // + KPROJ*DM/2          : half copy of W_out
#define YH_OFF   38871040ull     // + DM*DI/2             : half copy of Y
#define SCRATCH_TOTAL 40968192ull

// converter segment sizes (elements)
#define N_U  (BSTOT * DM)
#define N_WI (KPROJ * DM)
#define N_WO (DM * DI)

__device__ __align__(16) float g_scratch[SCRATCH_TOTAL];

__device__ __forceinline__ float softplusf(float x) {
    return x > 20.f ? x : log1pf(expf(x));
}
__device__ __forceinline__ float sigmoidf_(float x) {
    return 1.f / (1.f + expf(-x));
}

__device__ __forceinline__ void cp_async16h(__half* smem_dst, const __half* gsrc, bool pred) {
    unsigned int saddr = (unsigned int)__cvta_generic_to_shared(smem_dst);
    int sz = pred ? 16 : 0;
    asm volatile("cp.async.cg.shared.global [%0], [%1], 16, %2;\n"
                 :: "r"(saddr), "l"(gsrc), "r"(sz));
}
#define CP_COMMIT() asm volatile("cp.async.commit_group;\n" ::: "memory")
#define CP_WAIT(n)  asm volatile("cp.async.wait_group %0;\n" :: "n"(n) : "memory")

// split a float into hi/lo halves (v ~= hi + lo, ~22-bit effective precision)
__device__ __forceinline__ void split1(__half* hi, __half* lo, int off, float v) {
    __half h = __float2half_rn(v);
    hi[off] = h;
    lo[off] = __float2half_rn(v - __half2float(h));
}
__device__ __forceinline__ void split4(__half* hi, __half* lo, int off, float4 v) {
    split1(hi, lo, off + 0, v.x);
    split1(hi, lo, off + 1, v.y);
    split1(hi, lo, off + 2, v.z);
    split1(hi, lo, off + 3, v.w);
}

// ---------------------------------------------------------------------------
// Fused fp32 -> fp16 converter for u, W_in, W_out in ONE launch.
// ---------------------------------------------------------------------------
__global__ __launch_bounds__(256) void convert_all_kernel(
    const float* __restrict__ u,
    const float* __restrict__ W_in,
    const float* __restrict__ W_out)
{
    __half* u_h  = reinterpret_cast<__half*>(g_scratch + UH_OFF);
    __half* Wi_h = reinterpret_cast<__half*>(g_scratch + WIH_OFF);
    __half* Wo_h = reinterpret_cast<__half*>(g_scratch + WOH_OFF);

    const int total = (N_U + N_WI + N_WO) / 8;
    int idx = blockIdx.x * blockDim.x + threadIdx.x;
    int stride = gridDim.x * blockDim.x;

    for (; idx < total; idx += stride) {
        int i = idx * 8;
        const float* src;
        __half* dst;
        if (i < N_U)                { src = u + i;                dst = u_h + i; }
        else if (i < N_U + N_WI)    { src = W_in + (i - N_U);     dst = Wi_h + (i - N_U); }
        else                        { src = W_out + (i - N_U - N_WI); dst = Wo_h + (i - N_U - N_WI); }

        float4 v0 = *reinterpret_cast<const float4*>(src);
        float4 v1 = *reinterpret_cast<const float4*>(src + 4);
        __half2 h0 = __floats2half2_rn(v0.x, v0.y);
        __half2 h1 = __floats2half2_rn(v0.z, v0.w);
        __half2 h2 = __floats2half2_rn(v1.x, v1.y);
        __half2 h3 = __floats2half2_rn(v1.z, v1.w);
        uint4 pack;
        pack.x = *reinterpret_cast<unsigned int*>(&h0);
        pack.y = *reinterpret_cast<unsigned int*>(&h1);
        pack.z = *reinterpret_cast<unsigned int*>(&h2);
        pack.w = *reinterpret_cast<unsigned int*>(&h3);
        *reinterpret_cast<uint4*>(dst) = pack;
    }
}

// ---------------------------------------------------------------------------
// FP16 tensor-core NT GEMM (fp32 accumulate), cp.async 2-stage double buffer.
// ---------------------------------------------------------------------------
#define BKH 40

__global__ __launch_bounds__(256, 2) void hgemm_nt(
    int M, int N, int K,
    const __half* __restrict__ A,
    const __half* __restrict__ B,
    float* __restrict__ C)
{
    __shared__ __half As[2][128 * BKH];
    __shared__ __half Bs[2][128 * BKH];

    const int tid = threadIdx.x;
    const int wid = tid >> 5;
    const int m0 = blockIdx.y * 128;
    const int n0 = blockIdx.x * 128;
    const int wm = (wid & 1) * 64;
    const int wn = (wid >> 1) * 32;

    const int lrow = tid >> 2;
    const int lch  = (tid & 3) * 8;

    wmma::fragment<wmma::accumulator, 16, 16, 16, float> acc[4][2];
#pragma unroll
    for (int i = 0; i < 4; ++i)
#pragma unroll
        for (int j = 0; j < 2; ++j)
            wmma::fill_fragment(acc[i][j], 0.f);

    auto load_stage = [&](int s, int kt) {
#pragma unroll
        for (int i = 0; i < 2; ++i) {
            int row = i * 64 + lrow;
            cp_async16h(&As[s][row * BKH + lch],
                        A + (size_t)(m0 + row) * K + kt + lch, true);
            bool bp = (n0 + row) < N;
            cp_async16h(&Bs[s][row * BKH + lch],
                        B + (size_t)(n0 + row) * K + bp * ((size_t)kt + lch), bp);
        }
        CP_COMMIT();
    };

    const int nt = K >> 5;
    load_stage(0, 0);

    for (int it = 0; it < nt; ++it) {
        const int s = it & 1;
        if (it + 1 < nt) {
            load_stage(s ^ 1, (it + 1) << 5);
            CP_WAIT(1);
        } else {
            CP_WAIT(0);
        }
        __syncthreads();

        const __half* Asm = As[s];
        const __half* Bsm = Bs[s];
#pragma unroll
        for (int k16 = 0; k16 < 32; k16 += 16) {
            wmma::fragment<wmma::matrix_b, 16, 16, 16, __half, wmma::col_major> bf[2];
#pragma unroll
            for (int j = 0; j < 2; ++j)
                wmma::load_matrix_sync(bf[j], Bsm + (wn + j * 16) * BKH + k16, BKH);
#pragma unroll
            for (int i = 0; i < 4; ++i) {
                wmma::fragment<wmma::matrix_a, 16, 16, 16, __half, wmma::row_major> af;
                wmma::load_matrix_sync(af, Asm + (wm + i * 16) * BKH + k16, BKH);
                wmma::mma_sync(acc[i][0], af, bf[0], acc[i][0]);
                wmma::mma_sync(acc[i][1], af, bf[1], acc[i][1]);
            }
        }
        __syncthreads();
    }

#pragma unroll
    for (int i = 0; i < 4; ++i) {
#pragma unroll
        for (int j = 0; j < 2; ++j) {
            int cc = n0 + wn + j * 16;
            if (cc < N)
                wmma::store_matrix_sync(
                    C + (size_t)(m0 + wm + i * 16) * N + cc,
                    acc[i][j], N, wmma::mem_row_major);
        }
    }
}

// ---------------------------------------------------------------------------
// Prep (unchanged)
// ---------------------------------------------------------------------------
__global__ __launch_bounds__(128) void prep_kernel(
    const float* __restrict__ dt_bias,
    const float* __restrict__ B_bias,
    const float* __restrict__ C_bias,
    const float* __restrict__ Bn_w,
    const float* __restrict__ Cn_w)
{
    const int bs = blockIdx.x;
    const int tid = threadIdx.x;
    const float* row = g_scratch + PROJ_OFF + (size_t)bs * KPROJ;

    __shared__ float normB[64], normC[64];
    __shared__ float cs[16], sn[16];
    __shared__ float gdt_s[64];
    __shared__ float red[4];

    float v = (tid < 64) ? row[OFF_B + tid] : row[OFF_C + (tid - 64)];
    float sq = v * v;
#pragma unroll
    for (int o = 16; o > 0; o >>= 1) sq += __shfl_xor_sync(0xffffffffu, sq, o);
    if ((tid & 31) == 0) red[tid >> 5] = sq;
    __syncthreads();
    float rB = rsqrtf((red[0] + red[1]) * (1.f / 64.f) + EPSV);
    float rC = rsqrtf((red[2] + red[3]) * (1.f / 64.f) + EPSV);
    if (tid < 64) normB[tid] = v * rB * Bn_w[tid];
    else          normC[tid - 64] = v * rC * Cn_w[tid - 64];

    if (tid < 64) {
        int h = tid;
        float dt = softplusf(row[OFF_DT + h] + dt_bias[h]);
        float A  = fminf(-softplusf(row[OFF_A + h]), -1e-4f);
        float trap = sigmoidf_(row[OFF_TR + h]);
        float g = 1.f - 0.5f * trap;
        float a = g * expf(A * dt) + 0.5f * trap;
        g_scratch[AARR_OFF + (size_t)bs * NH + h] = a;
        gdt_s[h] = g * dt;
    }
    if (tid < 16) {
        float ang = row[OFF_ANG + tid];
        cs[tid] = cosf(ang);
        sn[tid] = sinf(ang);
    }
    __syncthreads();

    float* gb_out = g_scratch + GB_OFF + (size_t)bs * (NH * DS);
    float* cm_out = g_scratch + CM_OFF + (size_t)bs * (NH * DS);
#pragma unroll
    for (int it = 0; it < 32; ++it) {
        int i = it * 128 + tid;
        int h = i >> 6;
        int n = i & 63;
        float vB = normB[n] + B_bias[i];
        float vC = normC[n] + C_bias[i];
        float oB, oC;
        if (n < 16) {
            float b2 = normB[n + 16] + B_bias[h * 64 + n + 16];
            float c2 = normC[n + 16] + C_bias[h * 64 + n + 16];
            oB = vB * cs[n] - b2 * sn[n];
            oC = vC * cs[n] - c2 * sn[n];
        } else if (n < 32) {
            int j = n - 16;
            float b1 = normB[j] + B_bias[h * 64 + j];
            float c1 = normC[j] + C_bias[h * 64 + j];
            oB = b1 * sn[j] + vB * cs[j];
            oC = c1 * sn[j] + vC * cs[j];
        } else {
            oB = vB;
            oC = vC;
        }
        gb_out[i] = gdt_s[h] * oB;
        cm_out[i] = oC;
    }
}

// ---------------------------------------------------------------------------
// Pass 1 (SSD form), smem-optimized: M aliases the C buffers (C is dead after
// the G GEMM; the post-G __syncthreads orders the reuse). 65 KB smem -> 3 CTAs/SM.
// ---------------------------------------------------------------------------
#define LDT 72   // fp16 tile ld (64x64 tiles)
#define LDX 40   // fp16 tile ld (64x32 tiles)
#define LDG 68   // fp32 G buffer ld

#define SCAN_SMEM_BYTES ((64*LDG + 128) * 4 + (4 * 64*LDT + 2 * 64*LDX) * 2)

__global__ __launch_bounds__(256) void scan_chunk_mma(const float* __restrict__ Dv)
{
    extern __shared__ char dsm[];
    float* Gf = reinterpret_cast<float*>(dsm);           // 64*LDG
    float* af = Gf + 64 * LDG;                           // 64
    float* lp = af + 64;                                 // 64
    __half* Ch = reinterpret_cast<__half*>(lp + 64);
    __half* Cl = Ch + 64 * LDT;
    __half* Bh = Cl + 64 * LDT;
    __half* Bl = Bh + 64 * LDT;
    __half* Xh = Bl + 64 * LDT;
    __half* Xl = Xh + 64 * LDX;
    __half* Mh = Ch;          // alias: C dead after G GEMM
    __half* Ml = Cl;

    const int bx = blockIdx.x;
    const int c = bx & (NC - 1);
    const int h = (bx >> 4) & (NH - 1);
    const int b = bx >> 10;
    const int tid = threadIdx.x;
    const int w = tid >> 5;
    const int t0 = c * CHUNK;

    const float* proj = g_scratch + PROJ_OFF;
    const float* aarr = g_scratch + AARR_OFF;
    const float* gbb  = g_scratch + GB_OFF;
    const float* cmb  = g_scratch + CM_OFF;
    float* Yb = g_scratch + Y_OFF;
    float* Pb = g_scratch + PBUF_OFF;

    // ---- load C, gdtB (64x64) and X (64x32), split hi/lo
    const size_t rowstride = (size_t)NH * DS;
    const float* cbase = cmb + ((size_t)(b * SEQ + t0) * NH + h) * DS;
    const float* bbase = gbb + ((size_t)(b * SEQ + t0) * NH + h) * DS;
    for (int i = tid; i < 1024; i += 256) {
        int r = i >> 4, c4 = (i & 15) << 2;
        float4 v = *reinterpret_cast<const float4*>(cbase + (size_t)r * rowstride + c4);
        split4(Ch, Cl, r * LDT + c4, v);
        float4 u = *reinterpret_cast<const float4*>(bbase + (size_t)r * rowstride + c4);
        split4(Bh, Bl, r * LDT + c4, u);
    }
    const float* xbase = proj + (size_t)(b * SEQ + t0) * KPROJ + OFF_X + h * HD;
    for (int i = tid; i < 512; i += 256) {
        int r = i >> 3, c4 = (i & 7) << 2;
        float4 v = *reinterpret_cast<const float4*>(xbase + (size_t)r * KPROJ + c4);
        split4(Xh, Xl, r * LDX + c4, v);
    }
    if (tid < 64) af[tid] = aarr[((size_t)(b * SEQ + t0 + tid)) * NH + h];
    __syncthreads();

    // ---- log-space cumulative decay
    if (tid < 64) af[tid] = log2f(fmaxf(af[tid], 1e-37f));
    __syncthreads();
    if (tid == 0) {
        float L = 0.f;
        for (int t = 0; t < CHUNK; ++t) { L += af[t]; lp[t] = L; }
    }
    __syncthreads();
    if (tid < 64) Pb[((size_t)(b * SEQ + t0 + tid)) * NH + h] = exp2f(lp[tid]);

    // ---- G = C @ gdtB^T  (64x64x64), hi/lo 3-term
    {
        const int tr = w & 3;
        const int tcb = (w >> 2) * 2;
        wmma::fragment<wmma::accumulator, 16, 16, 16, float> acc[2];
        wmma::fill_fragment(acc[0], 0.f);
        wmma::fill_fragment(acc[1], 0.f);
#pragma unroll
        for (int ks = 0; ks < 64; ks += 16) {
            wmma::fragment<wmma::matrix_a, 16, 16, 16, __half, wmma::row_major> ah, al;
            wmma::load_matrix_sync(ah, Ch + tr * 16 * LDT + ks, LDT);
            wmma::load_matrix_sync(al, Cl + tr * 16 * LDT + ks, LDT);
#pragma unroll
            for (int j = 0; j < 2; ++j) {
                wmma::fragment<wmma::matrix_b, 16, 16, 16, __half, wmma::col_major> bhf, blf;
                wmma::load_matrix_sync(bhf, Bh + (tcb + j) * 16 * LDT + ks, LDT);
                wmma::load_matrix_sync(blf, Bl + (tcb + j) * 16 * LDT + ks, LDT);
                wmma::mma_sync(acc[j], ah, bhf, acc[j]);
                wmma::mma_sync(acc[j], ah, blf, acc[j]);
                wmma::mma_sync(acc[j], al, bhf, acc[j]);
            }
        }
        wmma::store_matrix_sync(Gf + tr * 16 * LDG + tcb * 16, acc[0], LDG, wmma::mem_row_major);
        wmma::store_matrix_sync(Gf + tr * 16 * LDG + (tcb + 1) * 16, acc[1], LDG, wmma::mem_row_major);
    }
    __syncthreads();   // G done; C buffers now reusable as M

    // ---- build masked M (into C-space), rescale B rows by exp2(lp[63]-lp[s])
    const float lpe = lp[63];
    for (int i = tid; i < 4096; i += 256) {
        int t = i >> 6, s = i & 63;
        float g = (s <= t) ? Gf[t * LDG + s] * exp2f(lp[t] - lp[s]) : 0.f;
        split1(Mh, Ml, t * LDT + s, g);
    }
    for (int i = tid; i < 4096; i += 256) {
        int s = i >> 6, n = i & 63;
        int off = s * LDT + n;
        float bv = __half2float(Bh[off]) + __half2float(Bl[off]);
        bv *= exp2f(lpe - lp[s]);
        split1(Bh, Bl, off, bv);
    }
    __syncthreads();

    // ---- Yloc = M @ X (64x32x64) -> global Yb ; Hend = X^T @ Bscaled -> HST
    {
        const int tr = w & 3;
        const int tc = w >> 2;          // 0..1
        wmma::fragment<wmma::accumulator, 16, 16, 16, float> accY;
        wmma::fill_fragment(accY, 0.f);
#pragma unroll
        for (int ks = 0; ks < 64; ks += 16) {
            wmma::fragment<wmma::matrix_a, 16, 16, 16, __half, wmma::row_major> ah, al;
            wmma::load_matrix_sync(ah, Mh + tr * 16 * LDT + ks, LDT);
            wmma::load_matrix_sync(al, Ml + tr * 16 * LDT + ks, LDT);
            wmma::fragment<wmma::matrix_b, 16, 16, 16, __half, wmma::row_major> bhf, blf;
            wmma::load_matrix_sync(bhf, Xh + ks * LDX + tc * 16, LDX);
            wmma::load_matrix_sync(blf, Xl + ks * LDX + tc * 16, LDX);
            wmma::mma_sync(accY, ah, bhf, accY);
            wmma::mma_sync(accY, ah, blf, accY);
            wmma::mma_sync(accY, al, bhf, accY);
        }
        float* yp = Yb + (size_t)(b * SEQ + t0 + tr * 16) * DI + h * HD + tc * 16;
        wmma::store_matrix_sync(yp, accY, DI, wmma::mem_row_major);

        const int pr = w & 1;           // 0..1 (p)
        const int nc = w >> 1;          // 0..3 (n)
        wmma::fragment<wmma::accumulator, 16, 16, 16, float> accH;
        wmma::fill_fragment(accH, 0.f);
#pragma unroll
        for (int ks = 0; ks < 64; ks += 16) {
            wmma::fragment<wmma::matrix_a, 16, 16, 16, __half, wmma::col_major> ah, al;
            wmma::load_matrix_sync(ah, Xh + pr * 16 + ks * LDX, LDX);
            wmma::load_matrix_sync(al, Xl + pr * 16 + ks * LDX, LDX);
            wmma::fragment<wmma::matrix_b, 16, 16, 16, __half, wmma::row_major> bhf, blf;
            wmma::load_matrix_sync(bhf, Bh + ks * LDT + nc * 16, LDT);
            wmma::load_matrix_sync(blf, Bl + ks * LDT + nc * 16, LDT);
            wmma::mma_sync(accH, ah, bhf, accH);
            wmma::mma_sync(accH, ah, blf, accH);
            wmma::mma_sync(accH, al, bhf, accH);
        }
        float* hp = g_scratch + HST_OFF +
                    (((size_t)(b * NH + h) * NC + c) * (HD * DS)) + (pr * 16) * DS + nc * 16;
        wmma::store_matrix_sync(hp, accH, DS, wmma::mem_row_major);
    }
}

// ---------------------------------------------------------------------------
// Pass 2: sequential combine of chunk states into prefix end-states.
// ---------------------------------------------------------------------------
__global__ __launch_bounds__(256) void combine_kernel()
{
    const int bh = blockIdx.x;
    const int b = bh >> 6;
    const int h = bh & 63;
    const int tid = threadIdx.x;
    const int e = tid * 8;

    float* base = g_scratch + HST_OFF + (size_t)bh * NC * (HD * DS);
    const float* Pb = g_scratch + PBUF_OFF;

    float4 H0 = reinterpret_cast<float4*>(base + e)[0];
    float4 H1 = reinterpret_cast<float4*>(base + e)[1];

    for (int c = 1; c < NC; ++c) {
        float Atot = Pb[((size_t)b * SEQ + c * CHUNK + CHUNK - 1) * NH + h];
        float* ptr = base + (size_t)c * (HD * DS) + e;
        float4 L0 = reinterpret_cast<float4*>(ptr)[0];
        float4 L1 = reinterpret_cast<float4*>(ptr)[1];
        H0.x = fmaf(Atot, H0.x, L0.x); H0.y = fmaf(Atot, H0.y, L0.y);
        H0.z = fmaf(Atot, H0.z, L0.z); H0.w = fmaf(Atot, H0.w, L0.w);
        H1.x = fmaf(Atot, H1.x, L1.x); H1.y = fmaf(Atot, H1.y, L1.y);
        H1.z = fmaf(Atot, H1.z, L1.z); H1.w = fmaf(Atot, H1.w, L1.w);
        reinterpret_cast<float4*>(ptr)[0] = H0;
        reinterpret_cast<float4*>(ptr)[1] = H1;
    }
}

// ---------------------------------------------------------------------------
// Pass 3 (SSD form): Ycorr = C @ Hprev; y = (Yloc + P*Ycorr + Dh*x)*silu(z).
// ---------------------------------------------------------------------------
__global__ __launch_bounds__(256) void fixup_mma(const float* __restrict__ Dv)
{
    __shared__ __half Ch[64 * LDT];
    __shared__ __half Cl[64 * LDT];
    __shared__ __half Hh[32 * LDT];   // col_major buf[n + p*LDT]
    __shared__ __half Hl[32 * LDT];
    __shared__ float Yc[64 * LDX];
    __shared__ float Pf[64];

    const int bx = blockIdx.x;
    const int c = bx & (NC - 1);
    const int h = (bx >> 4) & (NH - 1);
    const int b = bx >> 10;
    const int tid = threadIdx.x;
    const int w = tid >> 5;
    const int t0 = c * CHUNK;

    const float* proj = g_scratch + PROJ_OFF;
    const float* cmb  = g_scratch + CM_OFF;
    const float* Pb   = g_scratch + PBUF_OFF;
    const float* Yb   = g_scratch + Y_OFF;
    __half* Yh = reinterpret_cast<__half*>(g_scratch + YH_OFF);

    const float Dh = Dv[h];

    const size_t rowstride = (size_t)NH * DS;
    const float* cbase = cmb + ((size_t)(b * SEQ + t0) * NH + h) * DS;
    for (int i = tid; i < 1024; i += 256) {
        int r = i >> 4, c4 = (i & 15) << 2;
        float4 v = *reinterpret_cast<const float4*>(cbase + (size_t)r * rowstride + c4);
        split4(Ch, Cl, r * LDT + c4, v);
    }
    if (c > 0) {
        const float* hstp = g_scratch + HST_OFF +
            (((size_t)(b * NH + h) * NC + (c - 1)) * (HD * DS));
        for (int i = tid; i < 512; i += 256) {
            int r = i >> 4, c4 = (i & 15) << 2;   // r = p, c4 = n
            float4 v = *reinterpret_cast<const float4*>(hstp + r * DS + c4);
            split4(Hh, Hl, r * LDT + c4, v);
        }
    } else {
        for (int i = tid; i < 32 * LDT; i += 256) { Hh[i] = __float2half(0.f); Hl[i] = __float2half(0.f); }
    }
    if (tid < 64) Pf[tid] = Pb[((size_t)(b * SEQ + t0 + tid)) * NH + h];
    __syncthreads();

    // Ycorr = C @ Hprev : A row_major (t,n); B col_major buf[n + p*LDT]
    {
        const int tr = w & 3;
        const int tc = w >> 2;   // 0..1
        wmma::fragment<wmma::accumulator, 16, 16, 16, float> acc;
        wmma::fill_fragment(acc, 0.f);
#pragma unroll
        for (int ks = 0; ks < 64; ks += 16) {
            wmma::fragment<wmma::matrix_a, 16, 16, 16, __half, wmma::row_major> ah, al;
            wmma::load_matrix_sync(ah, Ch + tr * 16 * LDT + ks, LDT);
            wmma::load_matrix_sync(al, Cl + tr * 16 * LDT + ks, LDT);
            wmma::fragment<wmma::matrix_b, 16, 16, 16, __half, wmma::col_major> bhf, blf;
            wmma::load_matrix_sync(bhf, Hh + ks + (tc * 16) * LDT, LDT);
            wmma::load_matrix_sync(blf, Hl + ks + (tc * 16) * LDT, LDT);
            wmma::mma_sync(acc, ah, bhf, acc);
            wmma::mma_sync(acc, ah, blf, acc);
            wmma::mma_sync(acc, al, bhf, acc);
        }
        wmma::store_matrix_sync(Yc + tr * 16 * LDX + tc * 16, acc, LDX, wmma::mem_row_major);
    }
    __syncthreads();

    // epilogue: 8 elems per thread
    {
        const int t = tid >> 2;
        const int p0 = (tid & 3) << 3;
        const size_t bs = (size_t)b * SEQ + t0 + t;
        const float* yrow = Yb + bs * DI + h * HD + p0;
        const float* xrow = proj + bs * KPROJ + OFF_X + h * HD + p0;
        const float* zrow = proj + bs * KPROJ + OFF_Z + h * HD + p0;
        const float Pt = Pf[t];
        float r[8];
#pragma unroll
        for (int k = 0; k < 8; ++k) {
            float y = yrow[k] + Pt * Yc[t * LDX + p0 + k] + Dh * xrow[k];
            float z = zrow[k];
            r[k] = y * (z * sigmoidf_(z));
        }
        __half2 o0 = __floats2half2_rn(r[0], r[1]);
        __half2 o1 = __floats2half2_rn(r[2], r[3]);
        __half2 o2 = __floats2half2_rn(r[4], r[5]);
        __half2 o3 = __floats2half2_rn(r[6], r[7]);
        uint4 pack;
        pack.x = *reinterpret_cast<unsigned int*>(&o0);
        pack.y = *reinterpret_cast<unsigned int*>(&o1);
        pack.z = *reinterpret_cast<unsigned int*>(&o2);
        pack.w = *reinterpret_cast<unsigned int*>(&o3);
        *reinterpret_cast<uint4*>(Yh + bs * DI + h * HD + p0) = pack;
    }
}

// ---------------------------------------------------------------------------
extern "C" void kernel_launch(void* const* d_in, const int* in_sizes, int n_in,
                              void* d_out, int out_size)
{
    const float* u       = (const float*)d_in[0];
    const float* W_in    = (const float*)d_in[1];
    const float* dt_bias = (const float*)d_in[2];
    const float* B_bias  = (const float*)d_in[3];
    const float* C_bias  = (const float*)d_in[4];
    const float* Bn_w    = (const float*)d_in[5];
    const float* Cn_w    = (const float*)d_in[6];
    const float* Dv      = (const float*)d_in[7];
    const float* W_out   = (const float*)d_in[8];
    float* out = (float*)d_out;

    float* scratch = nullptr;
    cudaGetSymbolAddress((void**)&scratch, g_scratch);

    float* proj = scratch + PROJ_OFF;
    __half* u_h  = reinterpret_cast<__half*>(scratch + UH_OFF);
    __half* Wi_h = reinterpret_cast<__half*>(scratch + WIH_OFF);
    __half* Wo_h = reinterpret_cast<__half*>(scratch + WOH_OFF);
    __half* Yh   = reinterpret_cast<__half*>(scratch + YH_OFF);

    cudaFuncSetAttribute(scan_chunk_mma,
        cudaFuncAttributeMaxDynamicSharedMemorySize, SCAN_SMEM_BYTES);

    // Convert all GEMM operands to fp16 in ONE launch
    convert_all_kernel<<<888, 256>>>(u, W_in, W_out);

    // GEMM1: proj = u @ W_in^T
    {
        dim3 grid((KPROJ + 127) / 128, BSTOT / 128);
        hgemm_nt<<<grid, 256>>>(BSTOT, KPROJ, DM, u_h, Wi_h, proj);
    }

    prep_kernel<<<BSTOT, 128>>>(dt_bias, B_bias, C_bias, Bn_w, Cn_w);

    // chunked scan (SSD matrix form)
    scan_chunk_mma<<<NBATCH * NH * NC, 256, SCAN_SMEM_BYTES>>>(Dv);
    combine_kernel<<<NBATCH * NH, 256>>>();
    fixup_mma<<<NBATCH * NH * NC, 256>>>(Dv);

    // GEMM2: out = Y @ W_out^T
    {
        dim3 grid(DM / 128, BSTOT / 128);
        hgemm_nt<<<grid, 256>>>(BSTOT, DM, DI, Yh, Wo_h, out);
    }
}